// round 12
// baseline (speedup 1.0000x reference)
#include <cuda_runtime.h>
#include <cuda_fp16.h>
#include <cstdint>

#define EMBED    1024
#define HEADS    16
#define HEAD_DIM 64
#define BATCH    4
#define SEQ      2048
#define MTOT     (BATCH * SEQ)

// ---------------- scratch (no allocations allowed) ----------------
__device__ __half g_Qh [(size_t)MTOT * EMBED];   // projected Q [B,H,S,Dh]
__device__ __half g_Kh [(size_t)MTOT * EMBED];
__device__ __half g_Vh [(size_t)MTOT * EMBED];
__device__ __half g_ATTh[(size_t)MTOT * EMBED];  // attention out [B,S,E] fp16
__device__ __half g_Xqh[(size_t)MTOT * EMBED];   // fp16 copies of inputs
__device__ __half g_Xkh[(size_t)MTOT * EMBED];
__device__ __half g_Xvh[(size_t)MTOT * EMBED];
__device__ __half g_Wqh[(size_t)EMBED * EMBED];  // fp16 copies of weights
__device__ __half g_Wkh[(size_t)EMBED * EMBED];
__device__ __half g_Wvh[(size_t)EMBED * EMBED];
__device__ __half g_Woh[(size_t)EMBED * EMBED];

// ---------------- helpers ----------------
__device__ __forceinline__ uint32_t h2pack(float a, float b) {
    uint32_t r;
    asm("cvt.rn.f16x2.f32 %0, %1, %2;" : "=r"(r) : "f"(b), "f"(a));
    return r;
}

__device__ __forceinline__ float exp2a(float x) {
    float r;
    asm("ex2.approx.f32 %0, %1;" : "=f"(r) : "f"(x));
    return r;
}

__device__ __forceinline__ void mma_f16(
    float& c0, float& c1, float& c2, float& c3,
    uint32_t a0, uint32_t a1, uint32_t a2, uint32_t a3,
    uint32_t b0, uint32_t b1)
{
    asm volatile(
        "mma.sync.aligned.m16n8k16.row.col.f32.f16.f16.f32 "
        "{%0,%1,%2,%3}, {%4,%5,%6,%7}, {%8,%9}, {%0,%1,%2,%3};\n"
        : "+f"(c0), "+f"(c1), "+f"(c2), "+f"(c3)
        : "r"(a0), "r"(a1), "r"(a2), "r"(a3), "r"(b0), "r"(b1));
}

__device__ __forceinline__ uint32_t smem_u32(const void* p) {
    uint32_t a;
    asm("{ .reg .u64 t; cvta.to.shared.u64 t, %1; cvt.u32.u64 %0, t; }"
        : "=r"(a) : "l"(p));
    return a;
}

__device__ __forceinline__ void cp16(uint32_t dst, const void* src) {
    asm volatile("cp.async.cg.shared.global [%0], [%1], 16;" :: "r"(dst), "l"(src));
}
#define CP_COMMIT() asm volatile("cp.async.commit_group;" ::: "memory")
#define CP_WAIT0()  asm volatile("cp.async.wait_group 0;" ::: "memory")
#define CP_WAIT1()  asm volatile("cp.async.wait_group 1;" ::: "memory")

// ---------------- fp32 -> fp16 conversion pass ----------------
__global__ void to_half(const float4* __restrict__ in,
                        uint2* __restrict__ out, int n4)
{
    int i = blockIdx.x * blockDim.x + threadIdx.x;
    int stride = gridDim.x * blockDim.x;
    for (; i < n4; i += stride) {
        float4 v = in[i];
        out[i] = make_uint2(h2pack(v.x, v.y), h2pack(v.z, v.w));
    }
}

// ============================================================
// fp16 GEMM: C = A[.,1024] @ W[.,1024]^T + bias (x scale)
// A,W fp16 in gmem. CTA 256x128, 8 warps (4M x 2N), warp 64x64.
// BK=32, 2-stage cp.async ring. smem row stride 20 u32 (80B).
// MODE 0: float out row-major. MODE 1: half out scatter [B,H,S,Dh].
// ============================================================
#define GBM 256
#define GBN 128
#define GSTR 20
#define ABUF (GBM * GSTR)          // u32 per A stage
#define BBUF (GBN * GSTR)
#define STG  (ABUF + BBUF)
#define GT_SMEM_BYTES (2 * STG * 4)   // 61440
#define KITERS (EMBED / 32)

template <int MODE>
__device__ __forceinline__ void gemm_body(
    const __half* __restrict__ A, const __half* __restrict__ W,
    const float* __restrict__ bias, float* __restrict__ Cf,
    __half* __restrict__ Ch, float scale, int bm, int bn, uint32_t* sm)
{
    const int tid  = threadIdx.x;
    const int lane = tid & 31;
    const int warp = tid >> 5;
    const int wm   = warp >> 1;          // 0..3 -> 64 rows each
    const int wn   = warp & 1;           // 0..1 -> 64 cols each
    const int g    = lane >> 2;
    const int tg   = lane & 3;

    const uint32_t sbase = smem_u32(sm);

    // fill mappings
    const int arow = tid >> 2;           // +64*i  (4 iters -> 256 rows)
    const int achk = tid & 3;
    // B: 512 granules, 2 iters
    const int brow = tid >> 2;           // +64*i (2 iters -> 128 rows)

    auto fill = [&](int t, int s) {
        const uint32_t ab = sbase + (uint32_t)(s * STG) * 4;
        const uint32_t bb = ab + (uint32_t)ABUF * 4;
        const __half* Ap = A + (size_t)bm * EMBED + t * 32;
        const __half* Wp = W + (size_t)bn * EMBED + t * 32;
#pragma unroll
        for (int i = 0; i < 4; i++) {
            int r = arow + i * 64;
            cp16(ab + (uint32_t)(r * GSTR + achk * 4) * 4,
                 Ap + (size_t)r * EMBED + achk * 8);
        }
#pragma unroll
        for (int i = 0; i < 2; i++) {
            int r = brow + i * 64;
            cp16(bb + (uint32_t)(r * GSTR + achk * 4) * 4,
                 Wp + (size_t)r * EMBED + achk * 8);
        }
    };

    float acc[4][8][4];
#pragma unroll
    for (int i = 0; i < 4; i++)
#pragma unroll
        for (int j = 0; j < 8; j++)
#pragma unroll
            for (int v = 0; v < 4; v++) acc[i][j][v] = 0.f;

    fill(0, 0); CP_COMMIT();
    fill(1, 1); CP_COMMIT();

    for (int t = 0; t < KITERS; t++) {
        const int s = t & 1;
        if (t + 1 < KITERS) CP_WAIT1(); else CP_WAIT0();
        __syncthreads();

        const uint32_t* As = sm + s * STG;
        const uint32_t* Bs = As + ABUF;

#pragma unroll
        for (int ks = 0; ks < 2; ks++) {
            const int cb = ks * 8;
            uint32_t af[4][4];
#pragma unroll
            for (int mt = 0; mt < 4; mt++) {
                int mrow = wm * 64 + mt * 16 + g;
                af[mt][0] = As[mrow * GSTR + cb + tg];
                af[mt][1] = As[(mrow + 8) * GSTR + cb + tg];
                af[mt][2] = As[mrow * GSTR + cb + tg + 4];
                af[mt][3] = As[(mrow + 8) * GSTR + cb + tg + 4];
            }
#pragma unroll
            for (int nt = 0; nt < 8; nt++) {
                int nrow = wn * 64 + nt * 8 + g;
                uint32_t b0 = Bs[nrow * GSTR + cb + tg];
                uint32_t b1 = Bs[nrow * GSTR + cb + tg + 4];
#pragma unroll
                for (int mt = 0; mt < 4; mt++) {
                    mma_f16(acc[mt][nt][0], acc[mt][nt][1],
                            acc[mt][nt][2], acc[mt][nt][3],
                            af[mt][0], af[mt][1], af[mt][2], af[mt][3],
                            b0, b1);
                }
            }
        }
        __syncthreads();
        if (t + 2 < KITERS) { fill(t + 2, s); CP_COMMIT(); }
    }

    // epilogue
#pragma unroll
    for (int mt = 0; mt < 4; mt++) {
#pragma unroll
        for (int nt = 0; nt < 8; nt++) {
            int n = bn + wn * 64 + nt * 8 + tg * 2;
            float bia0 = bias[n], bia1 = bias[n + 1];
#pragma unroll
            for (int half = 0; half < 2; half++) {
                int m = bm + wm * 64 + mt * 16 + g + half * 8;
                float v0 = (acc[mt][nt][half * 2 + 0] + bia0) * scale;
                float v1 = (acc[mt][nt][half * 2 + 1] + bia1) * scale;
                if (MODE == 0) {
                    *reinterpret_cast<float2*>(&Cf[(size_t)m * EMBED + n]) =
                        make_float2(v0, v1);
                } else {
                    int b_ = m >> 11;
                    int s_ = m & (SEQ - 1);
                    int h_ = n >> 6;
                    int d_ = n & 63;
                    *reinterpret_cast<uint32_t*>(
                        &Ch[(((size_t)b_ * HEADS + h_) * SEQ + s_) * HEAD_DIM + d_]) =
                        h2pack(v0, v1);
                }
            }
        }
    }
}

__global__ __launch_bounds__(256) void gemm_qkv(
    const __half* __restrict__ xq, const __half* __restrict__ xk,
    const __half* __restrict__ xv,
    const __half* __restrict__ Wq, const __half* __restrict__ Wk,
    const __half* __restrict__ Wv,
    const float* __restrict__ bq, const float* __restrict__ bk,
    const float* __restrict__ bv,
    __half* __restrict__ oq, __half* __restrict__ ok, __half* __restrict__ ov)
{
    extern __shared__ __align__(16) uint32_t sm[];
    const __half *A, *W;
    const float* bias;
    __half* C;
    float scale = 1.0f;
    if (blockIdx.z == 0) {
        A = xq; W = Wq; bias = bq; C = oq;
        scale = 0.18033688011112042f;     // 1/sqrt(64) * log2(e)
    } else if (blockIdx.z == 1) {
        A = xk; W = Wk; bias = bk; C = ok;
    } else {
        A = xv; W = Wv; bias = bv; C = ov;
    }
    gemm_body<1>(A, W, bias, nullptr, C, scale,
                 blockIdx.y * GBM, blockIdx.x * GBN, sm);
}

__global__ __launch_bounds__(256) void gemm_out(
    const __half* __restrict__ A, const __half* __restrict__ W,
    const float* __restrict__ bias, float* __restrict__ C)
{
    extern __shared__ __align__(16) uint32_t sm[];
    gemm_body<0>(A, W, bias, C, nullptr, 1.0f,
                 blockIdx.y * GBM, blockIdx.x * GBN, sm);
}

// ============================================================
// fp16 flash attention (unchanged structure from R11; half output)
// ============================================================
#define FSTR 36
#define FBUF (64 * FSTR)

__global__ __launch_bounds__(256, 2) void flash_f16(
    const __half* __restrict__ Q, const __half* __restrict__ K,
    const __half* __restrict__ V, __half* __restrict__ Out)
{
    __shared__ __align__(16) uint32_t KS[2 * FBUF];
    __shared__ __align__(16) uint32_t VS[2 * FBUF];

    const int tid  = threadIdx.x;
    const int lane = tid & 31;
    const int w    = tid >> 5;
    const int g    = lane >> 2;
    const int tg   = lane & 3;

    const int qb = (int)gridDim.x - 1 - (int)blockIdx.x;
    const int bh = blockIdx.y;
    const int wrow = qb * 128 + w * 16;

    const uint32_t ksbase = smem_u32(KS);
    const __half* Kg = K + (size_t)bh * SEQ * HEAD_DIM;
    const __half* Vg = V + (size_t)bh * SEQ * HEAD_DIM;

    const __half* qbase = Q + ((size_t)bh * SEQ + wrow) * HEAD_DIM;
    uint32_t qf[4][4];
#pragma unroll
    for (int kk = 0; kk < 4; kk++) {
        int d0 = kk * 16 + 2 * tg;
        qf[kk][0] = *reinterpret_cast<const uint32_t*>(qbase + (size_t)g * 64 + d0);
        qf[kk][1] = *reinterpret_cast<const uint32_t*>(qbase + (size_t)(g + 8) * 64 + d0);
        qf[kk][2] = *reinterpret_cast<const uint32_t*>(qbase + (size_t)g * 64 + d0 + 8);
        qf[kk][3] = *reinterpret_cast<const uint32_t*>(qbase + (size_t)(g + 8) * 64 + d0 + 8);
    }

    float oacc[8][4];
#pragma unroll
    for (int nt = 0; nt < 8; nt++)
#pragma unroll
        for (int c = 0; c < 4; c++) oacc[nt][c] = 0.f;

    float m0 = -1e30f, m1 = -1e30f, l0 = 0.f, l1 = 0.f;

    const int kkey = tid >> 3;
    const int kchk = tid & 7;
    const int vkey2 = tid & 31;
    const int vd8   = tid >> 5;

    const int nbt = 2 * qb + 2;
    uint4 va, vb;

#pragma unroll
    for (int i = 0; i < 2; i++) {
        int key = kkey + i * 32;
        cp16(ksbase + (key * FSTR + kchk * 4) * 4, Kg + (size_t)key * 64 + kchk * 8);
    }
    CP_COMMIT();
    va = *reinterpret_cast<const uint4*>(Vg + (size_t)(2 * vkey2) * 64 + vd8 * 8);
    vb = *reinterpret_cast<const uint4*>(Vg + (size_t)(2 * vkey2 + 1) * 64 + vd8 * 8);
    {
        const uint32_t* au = reinterpret_cast<const uint32_t*>(&va);
        const uint32_t* bu = reinterpret_cast<const uint32_t*>(&vb);
#pragma unroll
        for (int j = 0; j < 8; j++) {
            uint32_t pk = (j & 1) ? __byte_perm(au[j >> 1], bu[j >> 1], 0x7632)
                                  : __byte_perm(au[j >> 1], bu[j >> 1], 0x5410);
            VS[(vd8 * 8 + j) * FSTR + vkey2] = pk;
        }
    }
    if (nbt > 1) {
        va = *reinterpret_cast<const uint4*>(Vg + (size_t)(64 + 2 * vkey2) * 64 + vd8 * 8);
        vb = *reinterpret_cast<const uint4*>(Vg + (size_t)(64 + 2 * vkey2 + 1) * 64 + vd8 * 8);
    }
    CP_WAIT0();
    __syncthreads();

    for (int kb = 0; kb < nbt; kb++) {
        const int s = kb & 1;
        const int ks = kb * 64;

        if (kb + 1 < nbt) {
            const int ksn = ks + 64;
#pragma unroll
            for (int i = 0; i < 2; i++) {
                int key = kkey + i * 32;
                cp16(ksbase + ((s ^ 1) * FBUF + key * FSTR + kchk * 4) * 4,
                     Kg + (size_t)(ksn + key) * 64 + kchk * 8);
            }
            CP_COMMIT();
            const uint32_t* au = reinterpret_cast<const uint32_t*>(&va);
            const uint32_t* bu = reinterpret_cast<const uint32_t*>(&vb);
            uint32_t* Vw = VS + (s ^ 1) * FBUF;
#pragma unroll
            for (int j = 0; j < 8; j++) {
                uint32_t pk = (j & 1) ? __byte_perm(au[j >> 1], bu[j >> 1], 0x7632)
                                      : __byte_perm(au[j >> 1], bu[j >> 1], 0x5410);
                Vw[(vd8 * 8 + j) * FSTR + vkey2] = pk;
            }
            if (kb + 2 < nbt) {
                const int ks2 = ks + 128;
                va = *reinterpret_cast<const uint4*>(
                    Vg + (size_t)(ks2 + 2 * vkey2) * 64 + vd8 * 8);
                vb = *reinterpret_cast<const uint4*>(
                    Vg + (size_t)(ks2 + 2 * vkey2 + 1) * 64 + vd8 * 8);
            }
        }

        const uint32_t* Kb = KS + s * FBUF;
        const uint32_t* Vb = VS + s * FBUF;

        if (ks <= wrow + 15) {
            float sacc[8][4];
#pragma unroll
            for (int nt = 0; nt < 8; nt++)
#pragma unroll
                for (int c = 0; c < 4; c++) sacc[nt][c] = 0.f;

#pragma unroll
            for (int kk = 0; kk < 4; kk++) {
#pragma unroll
                for (int nt = 0; nt < 8; nt++) {
                    uint32_t b0 = Kb[(nt * 8 + g) * FSTR + kk * 8 + tg];
                    uint32_t b1 = Kb[(nt * 8 + g) * FSTR + kk * 8 + tg + 4];
                    mma_f16(sacc[nt][0], sacc[nt][1], sacc[nt][2], sacc[nt][3],
                            qf[kk][0], qf[kk][1], qf[kk][2], qf[kk][3], b0, b1);
                }
            }

            if (ks + 64 > wrow) {
#pragma unroll
                for (int nt = 0; nt < 8; nt++) {
                    int col = ks + nt * 8 + 2 * tg;
                    if (col     > wrow + g)     sacc[nt][0] = -1e30f;
                    if (col + 1 > wrow + g)     sacc[nt][1] = -1e30f;
                    if (col     > wrow + g + 8) sacc[nt][2] = -1e30f;
                    if (col + 1 > wrow + g + 8) sacc[nt][3] = -1e30f;
                }
            }

            float rm0 = -1e30f, rm1 = -1e30f;
#pragma unroll
            for (int nt = 0; nt < 8; nt++) {
                rm0 = fmaxf(rm0, fmaxf(sacc[nt][0], sacc[nt][1]));
                rm1 = fmaxf(rm1, fmaxf(sacc[nt][2], sacc[nt][3]));
            }
            rm0 = fmaxf(rm0, __shfl_xor_sync(0xffffffffu, rm0, 1));
            rm0 = fmaxf(rm0, __shfl_xor_sync(0xffffffffu, rm0, 2));
            rm1 = fmaxf(rm1, __shfl_xor_sync(0xffffffffu, rm1, 1));
            rm1 = fmaxf(rm1, __shfl_xor_sync(0xffffffffu, rm1, 2));

            float mn0 = fmaxf(m0, rm0), mn1 = fmaxf(m1, rm1);
            float a0 = exp2a(m0 - mn0), a1 = exp2a(m1 - mn1);
            m0 = mn0; m1 = mn1;

            float ls0 = 0.f, ls1 = 0.f;
#pragma unroll
            for (int nt = 0; nt < 8; nt++) {
                float p0 = exp2a(sacc[nt][0] - mn0);
                float p1 = exp2a(sacc[nt][1] - mn0);
                float p2 = exp2a(sacc[nt][2] - mn1);
                float p3 = exp2a(sacc[nt][3] - mn1);
                sacc[nt][0] = p0; sacc[nt][1] = p1;
                sacc[nt][2] = p2; sacc[nt][3] = p3;
                ls0 += p0 + p1; ls1 += p2 + p3;
            }
            ls0 += __shfl_xor_sync(0xffffffffu, ls0, 1);
            ls0 += __shfl_xor_sync(0xffffffffu, ls0, 2);
            ls1 += __shfl_xor_sync(0xffffffffu, ls1, 1);
            ls1 += __shfl_xor_sync(0xffffffffu, ls1, 2);
            l0 = l0 * a0 + ls0;
            l1 = l1 * a1 + ls1;

#pragma unroll
            for (int nt = 0; nt < 8; nt++) {
                oacc[nt][0] *= a0; oacc[nt][1] *= a0;
                oacc[nt][2] *= a1; oacc[nt][3] *= a1;
            }

#pragma unroll
            for (int kk = 0; kk < 4; kk++) {
                uint32_t pa0 = h2pack(sacc[2 * kk][0],     sacc[2 * kk][1]);
                uint32_t pa1 = h2pack(sacc[2 * kk][2],     sacc[2 * kk][3]);
                uint32_t pa2 = h2pack(sacc[2 * kk + 1][0], sacc[2 * kk + 1][1]);
                uint32_t pa3 = h2pack(sacc[2 * kk + 1][2], sacc[2 * kk + 1][3]);
#pragma unroll
                for (int nt = 0; nt < 8; nt++) {
                    uint32_t b0 = Vb[(nt * 8 + g) * FSTR + kk * 8 + tg];
                    uint32_t b1 = Vb[(nt * 8 + g) * FSTR + kk * 8 + tg + 4];
                    mma_f16(oacc[nt][0], oacc[nt][1], oacc[nt][2], oacc[nt][3],
                            pa0, pa1, pa2, pa3, b0, b1);
                }
            }
        }

        if (kb + 1 < nbt) CP_WAIT0();
        __syncthreads();
    }

    // epilogue: divide by l, scatter fp16 to [B,S,EMBED]
    float inv0 = 1.f / l0, inv1 = 1.f / l1;
    int b_ = bh >> 4, h_ = bh & 15;
    int r0 = wrow + g, r1 = wrow + g + 8;
    __half* o0 = Out + ((size_t)b_ * SEQ + r0) * EMBED + h_ * 64;
    __half* o1 = Out + ((size_t)b_ * SEQ + r1) * EMBED + h_ * 64;
#pragma unroll
    for (int nt = 0; nt < 8; nt++) {
        *reinterpret_cast<uint32_t*>(&o0[nt * 8 + 2 * tg]) =
            h2pack(oacc[nt][0] * inv0, oacc[nt][1] * inv0);
        *reinterpret_cast<uint32_t*>(&o1[nt * 8 + 2 * tg]) =
            h2pack(oacc[nt][2] * inv1, oacc[nt][3] * inv1);
    }
}

// ---------------- launch ----------------
extern "C" void kernel_launch(void* const* d_in, const int* in_sizes, int n_in,
                              void* d_out, int out_size)
{
    const float* query  = (const float*)d_in[0];
    const float* key_in = (const float*)d_in[1];
    const float* value  = (const float*)d_in[2];
    // d_in[3] = mask (int32 tril) — causal applied analytically
    const float* Wq = (const float*)d_in[4];
    const float* bq = (const float*)d_in[5];
    const float* Wk = (const float*)d_in[6];
    const float* bk = (const float*)d_in[7];
    const float* Wv = (const float*)d_in[8];
    const float* bv = (const float*)d_in[9];
    const float* Wo = (const float*)d_in[10];
    const float* bo = (const float*)d_in[11];
    float* out = (float*)d_out;

    __half *gq, *gk, *gv, *ga, *xq, *xk, *xv, *wq, *wk, *wv, *wo;
    cudaGetSymbolAddress((void**)&gq, g_Qh);
    cudaGetSymbolAddress((void**)&gk, g_Kh);
    cudaGetSymbolAddress((void**)&gv, g_Vh);
    cudaGetSymbolAddress((void**)&ga, g_ATTh);
    cudaGetSymbolAddress((void**)&xq, g_Xqh);
    cudaGetSymbolAddress((void**)&xk, g_Xkh);
    cudaGetSymbolAddress((void**)&xv, g_Xvh);
    cudaGetSymbolAddress((void**)&wq, g_Wqh);
    cudaGetSymbolAddress((void**)&wk, g_Wkh);
    cudaGetSymbolAddress((void**)&wv, g_Wvh);
    cudaGetSymbolAddress((void**)&wo, g_Woh);

    cudaFuncSetAttribute(gemm_qkv,
                         cudaFuncAttributeMaxDynamicSharedMemorySize, GT_SMEM_BYTES);
    cudaFuncSetAttribute(gemm_out,
                         cudaFuncAttributeMaxDynamicSharedMemorySize, GT_SMEM_BYTES);

    const int NX4 = MTOT * EMBED / 4;
    const int NW4 = EMBED * EMBED / 4;
    to_half<<<1024, 256>>>((const float4*)query,  (uint2*)xq, NX4);
    to_half<<<1024, 256>>>((const float4*)key_in, (uint2*)xk, NX4);
    to_half<<<1024, 256>>>((const float4*)value,  (uint2*)xv, NX4);
    to_half<<<512, 256>>>((const float4*)Wq, (uint2*)wq, NW4);
    to_half<<<512, 256>>>((const float4*)Wk, (uint2*)wk, NW4);
    to_half<<<512, 256>>>((const float4*)Wv, (uint2*)wv, NW4);
    to_half<<<512, 256>>>((const float4*)Wo, (uint2*)wo, NW4);

    dim3 gqkv(EMBED / GBN, MTOT / GBM, 3);   // (8, 32, 3)
    gemm_qkv<<<gqkv, 256, GT_SMEM_BYTES>>>(xq, xk, xv, wq, wk, wv,
                                           bq, bk, bv, gq, gk, gv);

    flash_f16<<<dim3(SEQ / 128, BATCH * HEADS), 256>>>(gq, gk, gv, ga);

    gemm_out<<<dim3(EMBED / GBN, MTOT / GBM), 256, GT_SMEM_BYTES>>>(ga, wo, bo, out);
}

// round 13
// speedup vs baseline: 1.0581x; 1.0581x over previous
#include <cuda_runtime.h>
#include <cuda_fp16.h>
#include <cstdint>

#define EMBED    1024
#define HEADS    16
#define HEAD_DIM 64
#define BATCH    4
#define SEQ      2048
#define MTOT     (BATCH * SEQ)

// ---------------- scratch (no allocations allowed) ----------------
__device__ __half g_Qh [(size_t)MTOT * EMBED];
__device__ __half g_Kh [(size_t)MTOT * EMBED];
__device__ __half g_Vh [(size_t)MTOT * EMBED];
__device__ __half g_ATTh[(size_t)MTOT * EMBED];
__device__ __half g_Xqh[(size_t)MTOT * EMBED];
__device__ __half g_Xkh[(size_t)MTOT * EMBED];
__device__ __half g_Xvh[(size_t)MTOT * EMBED];
__device__ __half g_Wqh[(size_t)EMBED * EMBED];
__device__ __half g_Wkh[(size_t)EMBED * EMBED];
__device__ __half g_Wvh[(size_t)EMBED * EMBED];
__device__ __half g_Woh[(size_t)EMBED * EMBED];

// ---------------- helpers ----------------
__device__ __forceinline__ uint32_t h2pack(float a, float b) {
    uint32_t r;
    asm("cvt.rn.f16x2.f32 %0, %1, %2;" : "=r"(r) : "f"(b), "f"(a));
    return r;
}

__device__ __forceinline__ float exp2a(float x) {
    float r;
    asm("ex2.approx.f32 %0, %1;" : "=f"(r) : "f"(x));
    return r;
}

__device__ __forceinline__ void mma_f16(
    float& c0, float& c1, float& c2, float& c3,
    uint32_t a0, uint32_t a1, uint32_t a2, uint32_t a3,
    uint32_t b0, uint32_t b1)
{
    asm volatile(
        "mma.sync.aligned.m16n8k16.row.col.f32.f16.f16.f32 "
        "{%0,%1,%2,%3}, {%4,%5,%6,%7}, {%8,%9}, {%0,%1,%2,%3};\n"
        : "+f"(c0), "+f"(c1), "+f"(c2), "+f"(c3)
        : "r"(a0), "r"(a1), "r"(a2), "r"(a3), "r"(b0), "r"(b1));
}

__device__ __forceinline__ uint32_t smem_u32(const void* p) {
    uint32_t a;
    asm("{ .reg .u64 t; cvta.to.shared.u64 t, %1; cvt.u32.u64 %0, t; }"
        : "=r"(a) : "l"(p));
    return a;
}

__device__ __forceinline__ void cp16(uint32_t dst, const void* src) {
    asm volatile("cp.async.cg.shared.global [%0], [%1], 16;" :: "r"(dst), "l"(src));
}
#define CP_COMMIT() asm volatile("cp.async.commit_group;" ::: "memory")
#define CP_WAIT0()  asm volatile("cp.async.wait_group 0;" ::: "memory")
#define CP_WAIT1()  asm volatile("cp.async.wait_group 1;" ::: "memory")

// ---------------- fused fp32 -> fp16 conversion (7 tensors, one launch) ---
__global__ void to_half_all(
    const float4* __restrict__ q,  const float4* __restrict__ k,
    const float4* __restrict__ v,
    const float4* __restrict__ wq, const float4* __restrict__ wk,
    const float4* __restrict__ wv, const float4* __restrict__ wo,
    uint2* __restrict__ oq, uint2* __restrict__ ok, uint2* __restrict__ ov,
    uint2* __restrict__ owq, uint2* __restrict__ owk,
    uint2* __restrict__ owv, uint2* __restrict__ owo)
{
    const float4* in;
    uint2* out;
    int n4;
    switch (blockIdx.y) {
        case 0: in = q;  out = oq;  n4 = MTOT * EMBED / 4; break;
        case 1: in = k;  out = ok;  n4 = MTOT * EMBED / 4; break;
        case 2: in = v;  out = ov;  n4 = MTOT * EMBED / 4; break;
        case 3: in = wq; out = owq; n4 = EMBED * EMBED / 4; break;
        case 4: in = wk; out = owk; n4 = EMBED * EMBED / 4; break;
        case 5: in = wv; out = owv; n4 = EMBED * EMBED / 4; break;
        default: in = wo; out = owo; n4 = EMBED * EMBED / 4; break;
    }
    int i = blockIdx.x * blockDim.x + threadIdx.x;
    int stride = gridDim.x * blockDim.x;
    for (; i < n4; i += stride) {
        float4 x = in[i];
        out[i] = make_uint2(h2pack(x.x, x.y), h2pack(x.z, x.w));
    }
}

// ============================================================
// fp16 GEMM: C = A[.,1024] @ W[.,1024]^T + bias (x scale)
// fp16 operands in gmem, direct cp.async fills, 3-stage ring,
// one __syncthreads per K-iter. CTA 128x128, 8 warps, warp 32x64.
// MODE 0: float out row-major. MODE 1: half out scatter [B,H,S,Dh].
// ============================================================
#define GBM 128
#define GBN 128
#define GSTR 20                        // u32 per row (80B)
#define STG ((GBM + GBN) * GSTR)       // 5120 u32 per stage
#define NSTAGE 3
#define GT_SMEM_BYTES (NSTAGE * STG * 4)   // 61440
#define KITERS (EMBED / 32)

template <int MODE>
__device__ __forceinline__ void gemm_body(
    const __half* __restrict__ A, const __half* __restrict__ W,
    const float* __restrict__ bias, float* __restrict__ Cf,
    __half* __restrict__ Ch, float scale, int bm, int bn, uint32_t* sm)
{
    const int tid  = threadIdx.x;
    const int lane = tid & 31;
    const int warp = tid >> 5;
    const int wm   = warp >> 1;          // 0..3
    const int wn   = warp & 1;           // 0..1
    const int g    = lane >> 2;
    const int tg   = lane & 3;

    const uint32_t sbase = smem_u32(sm);
    const int frow = tid >> 2;           // 0..63 (+64 per i)
    const int fchk = tid & 3;            // 16B chunk

    auto fill = [&](int t) {
        const int s = t % NSTAGE;
        const uint32_t ab = sbase + (uint32_t)(s * STG) * 4;
        const uint32_t bb = ab + (uint32_t)(GBM * GSTR) * 4;
        const __half* Ap = A + (size_t)bm * EMBED + t * 32;
        const __half* Wp = W + (size_t)bn * EMBED + t * 32;
#pragma unroll
        for (int i = 0; i < 2; i++) {
            int r = frow + i * 64;
            cp16(ab + (uint32_t)(r * GSTR + fchk * 4) * 4,
                 Ap + (size_t)r * EMBED + fchk * 8);
            cp16(bb + (uint32_t)(r * GSTR + fchk * 4) * 4,
                 Wp + (size_t)r * EMBED + fchk * 8);
        }
    };

    float acc[2][8][4];
#pragma unroll
    for (int i = 0; i < 2; i++)
#pragma unroll
        for (int j = 0; j < 8; j++)
#pragma unroll
            for (int v = 0; v < 4; v++) acc[i][j][v] = 0.f;

    fill(0); CP_COMMIT();
    fill(1); CP_COMMIT();

    for (int t = 0; t < KITERS; t++) {
        if (t + 1 < KITERS) CP_WAIT1(); else CP_WAIT0();
        __syncthreads();
        if (t + 2 < KITERS) { fill(t + 2); CP_COMMIT(); }

        const uint32_t* As = sm + (t % NSTAGE) * STG;
        const uint32_t* Bs = As + GBM * GSTR;

#pragma unroll
        for (int ks = 0; ks < 2; ks++) {
            const int cb = ks * 8;
            uint32_t af[2][4];
#pragma unroll
            for (int mt = 0; mt < 2; mt++) {
                int mrow = wm * 32 + mt * 16 + g;
                af[mt][0] = As[mrow * GSTR + cb + tg];
                af[mt][1] = As[(mrow + 8) * GSTR + cb + tg];
                af[mt][2] = As[mrow * GSTR + cb + tg + 4];
                af[mt][3] = As[(mrow + 8) * GSTR + cb + tg + 4];
            }
#pragma unroll
            for (int nt = 0; nt < 8; nt++) {
                int nrow = wn * 64 + nt * 8 + g;
                uint32_t b0 = Bs[nrow * GSTR + cb + tg];
                uint32_t b1 = Bs[nrow * GSTR + cb + tg + 4];
#pragma unroll
                for (int mt = 0; mt < 2; mt++) {
                    mma_f16(acc[mt][nt][0], acc[mt][nt][1],
                            acc[mt][nt][2], acc[mt][nt][3],
                            af[mt][0], af[mt][1], af[mt][2], af[mt][3],
                            b0, b1);
                }
            }
        }
    }

    // epilogue
#pragma unroll
    for (int mt = 0; mt < 2; mt++) {
#pragma unroll
        for (int nt = 0; nt < 8; nt++) {
            int n = bn + wn * 64 + nt * 8 + tg * 2;
            float bia0 = bias[n], bia1 = bias[n + 1];
#pragma unroll
            for (int half = 0; half < 2; half++) {
                int m = bm + wm * 32 + mt * 16 + g + half * 8;
                float v0 = (acc[mt][nt][half * 2 + 0] + bia0) * scale;
                float v1 = (acc[mt][nt][half * 2 + 1] + bia1) * scale;
                if (MODE == 0) {
                    *reinterpret_cast<float2*>(&Cf[(size_t)m * EMBED + n]) =
                        make_float2(v0, v1);
                } else {
                    int b_ = m >> 11;
                    int s_ = m & (SEQ - 1);
                    int h_ = n >> 6;
                    int d_ = n & 63;
                    *reinterpret_cast<uint32_t*>(
                        &Ch[(((size_t)b_ * HEADS + h_) * SEQ + s_) * HEAD_DIM + d_]) =
                        h2pack(v0, v1);
                }
            }
        }
    }
}

__global__ __launch_bounds__(256, 2) void gemm_qkv(
    const __half* __restrict__ xq, const __half* __restrict__ xk,
    const __half* __restrict__ xv,
    const __half* __restrict__ Wq, const __half* __restrict__ Wk,
    const __half* __restrict__ Wv,
    const float* __restrict__ bq, const float* __restrict__ bk,
    const float* __restrict__ bv,
    __half* __restrict__ oq, __half* __restrict__ ok, __half* __restrict__ ov)
{
    extern __shared__ __align__(16) uint32_t sm[];
    const __half *A, *W;
    const float* bias;
    __half* C;
    float scale = 1.0f;
    if (blockIdx.z == 0) {
        A = xq; W = Wq; bias = bq; C = oq;
        scale = 0.18033688011112042f;     // 1/sqrt(64) * log2(e)
    } else if (blockIdx.z == 1) {
        A = xk; W = Wk; bias = bk; C = ok;
    } else {
        A = xv; W = Wv; bias = bv; C = ov;
    }
    gemm_body<1>(A, W, bias, nullptr, C, scale,
                 blockIdx.y * GBM, blockIdx.x * GBN, sm);
}

__global__ __launch_bounds__(256, 2) void gemm_out(
    const __half* __restrict__ A, const __half* __restrict__ W,
    const float* __restrict__ bias, float* __restrict__ C)
{
    extern __shared__ __align__(16) uint32_t sm[];
    gemm_body<0>(A, W, bias, C, nullptr, 1.0f,
                 blockIdx.y * GBM, blockIdx.x * GBN, sm);
}

// ============================================================
// fp16 flash attention (R12 structure, unchanged)
// ============================================================
#define FSTR 36
#define FBUF (64 * FSTR)

__global__ __launch_bounds__(256, 2) void flash_f16(
    const __half* __restrict__ Q, const __half* __restrict__ K,
    const __half* __restrict__ V, __half* __restrict__ Out)
{
    __shared__ __align__(16) uint32_t KS[2 * FBUF];
    __shared__ __align__(16) uint32_t VS[2 * FBUF];

    const int tid  = threadIdx.x;
    const int lane = tid & 31;
    const int w    = tid >> 5;
    const int g    = lane >> 2;
    const int tg   = lane & 3;

    const int qb = (int)gridDim.x - 1 - (int)blockIdx.x;
    const int bh = blockIdx.y;
    const int wrow = qb * 128 + w * 16;

    const uint32_t ksbase = smem_u32(KS);
    const __half* Kg = K + (size_t)bh * SEQ * HEAD_DIM;
    const __half* Vg = V + (size_t)bh * SEQ * HEAD_DIM;

    const __half* qbase = Q + ((size_t)bh * SEQ + wrow) * HEAD_DIM;
    uint32_t qf[4][4];
#pragma unroll
    for (int kk = 0; kk < 4; kk++) {
        int d0 = kk * 16 + 2 * tg;
        qf[kk][0] = *reinterpret_cast<const uint32_t*>(qbase + (size_t)g * 64 + d0);
        qf[kk][1] = *reinterpret_cast<const uint32_t*>(qbase + (size_t)(g + 8) * 64 + d0);
        qf[kk][2] = *reinterpret_cast<const uint32_t*>(qbase + (size_t)g * 64 + d0 + 8);
        qf[kk][3] = *reinterpret_cast<const uint32_t*>(qbase + (size_t)(g + 8) * 64 + d0 + 8);
    }

    float oacc[8][4];
#pragma unroll
    for (int nt = 0; nt < 8; nt++)
#pragma unroll
        for (int c = 0; c < 4; c++) oacc[nt][c] = 0.f;

    float m0 = -1e30f, m1 = -1e30f, l0 = 0.f, l1 = 0.f;

    const int kkey = tid >> 3;
    const int kchk = tid & 7;
    const int vkey2 = tid & 31;
    const int vd8   = tid >> 5;

    const int nbt = 2 * qb + 2;
    uint4 va, vb;

#pragma unroll
    for (int i = 0; i < 2; i++) {
        int key = kkey + i * 32;
        cp16(ksbase + (key * FSTR + kchk * 4) * 4, Kg + (size_t)key * 64 + kchk * 8);
    }
    CP_COMMIT();
    va = *reinterpret_cast<const uint4*>(Vg + (size_t)(2 * vkey2) * 64 + vd8 * 8);
    vb = *reinterpret_cast<const uint4*>(Vg + (size_t)(2 * vkey2 + 1) * 64 + vd8 * 8);
    {
        const uint32_t* au = reinterpret_cast<const uint32_t*>(&va);
        const uint32_t* bu = reinterpret_cast<const uint32_t*>(&vb);
#pragma unroll
        for (int j = 0; j < 8; j++) {
            uint32_t pk = (j & 1) ? __byte_perm(au[j >> 1], bu[j >> 1], 0x7632)
                                  : __byte_perm(au[j >> 1], bu[j >> 1], 0x5410);
            VS[(vd8 * 8 + j) * FSTR + vkey2] = pk;
        }
    }
    if (nbt > 1) {
        va = *reinterpret_cast<const uint4*>(Vg + (size_t)(64 + 2 * vkey2) * 64 + vd8 * 8);
        vb = *reinterpret_cast<const uint4*>(Vg + (size_t)(64 + 2 * vkey2 + 1) * 64 + vd8 * 8);
    }
    CP_WAIT0();
    __syncthreads();

    for (int kb = 0; kb < nbt; kb++) {
        const int s = kb & 1;
        const int ks = kb * 64;

        if (kb + 1 < nbt) {
            const int ksn = ks + 64;
#pragma unroll
            for (int i = 0; i < 2; i++) {
                int key = kkey + i * 32;
                cp16(ksbase + ((s ^ 1) * FBUF + key * FSTR + kchk * 4) * 4,
                     Kg + (size_t)(ksn + key) * 64 + kchk * 8);
            }
            CP_COMMIT();
            const uint32_t* au = reinterpret_cast<const uint32_t*>(&va);
            const uint32_t* bu = reinterpret_cast<const uint32_t*>(&vb);
            uint32_t* Vw = VS + (s ^ 1) * FBUF;
#pragma unroll
            for (int j = 0; j < 8; j++) {
                uint32_t pk = (j & 1) ? __byte_perm(au[j >> 1], bu[j >> 1], 0x7632)
                                      : __byte_perm(au[j >> 1], bu[j >> 1], 0x5410);
                Vw[(vd8 * 8 + j) * FSTR + vkey2] = pk;
            }
            if (kb + 2 < nbt) {
                const int ks2 = ks + 128;
                va = *reinterpret_cast<const uint4*>(
                    Vg + (size_t)(ks2 + 2 * vkey2) * 64 + vd8 * 8);
                vb = *reinterpret_cast<const uint4*>(
                    Vg + (size_t)(ks2 + 2 * vkey2 + 1) * 64 + vd8 * 8);
            }
        }

        const uint32_t* Kb = KS + s * FBUF;
        const uint32_t* Vb = VS + s * FBUF;

        if (ks <= wrow + 15) {
            float sacc[8][4];
#pragma unroll
            for (int nt = 0; nt < 8; nt++)
#pragma unroll
                for (int c = 0; c < 4; c++) sacc[nt][c] = 0.f;

#pragma unroll
            for (int kk = 0; kk < 4; kk++) {
#pragma unroll
                for (int nt = 0; nt < 8; nt++) {
                    uint32_t b0 = Kb[(nt * 8 + g) * FSTR + kk * 8 + tg];
                    uint32_t b1 = Kb[(nt * 8 + g) * FSTR + kk * 8 + tg + 4];
                    mma_f16(sacc[nt][0], sacc[nt][1], sacc[nt][2], sacc[nt][3],
                            qf[kk][0], qf[kk][1], qf[kk][2], qf[kk][3], b0, b1);
                }
            }

            if (ks + 64 > wrow) {
#pragma unroll
                for (int nt = 0; nt < 8; nt++) {
                    int col = ks + nt * 8 + 2 * tg;
                    if (col     > wrow + g)     sacc[nt][0] = -1e30f;
                    if (col + 1 > wrow + g)     sacc[nt][1] = -1e30f;
                    if (col     > wrow + g + 8) sacc[nt][2] = -1e30f;
                    if (col + 1 > wrow + g + 8) sacc[nt][3] = -1e30f;
                }
            }

            float rm0 = -1e30f, rm1 = -1e30f;
#pragma unroll
            for (int nt = 0; nt < 8; nt++) {
                rm0 = fmaxf(rm0, fmaxf(sacc[nt][0], sacc[nt][1]));
                rm1 = fmaxf(rm1, fmaxf(sacc[nt][2], sacc[nt][3]));
            }
            rm0 = fmaxf(rm0, __shfl_xor_sync(0xffffffffu, rm0, 1));
            rm0 = fmaxf(rm0, __shfl_xor_sync(0xffffffffu, rm0, 2));
            rm1 = fmaxf(rm1, __shfl_xor_sync(0xffffffffu, rm1, 1));
            rm1 = fmaxf(rm1, __shfl_xor_sync(0xffffffffu, rm1, 2));

            float mn0 = fmaxf(m0, rm0), mn1 = fmaxf(m1, rm1);
            float a0 = exp2a(m0 - mn0), a1 = exp2a(m1 - mn1);
            m0 = mn0; m1 = mn1;

            float ls0 = 0.f, ls1 = 0.f;
#pragma unroll
            for (int nt = 0; nt < 8; nt++) {
                float p0 = exp2a(sacc[nt][0] - mn0);
                float p1 = exp2a(sacc[nt][1] - mn0);
                float p2 = exp2a(sacc[nt][2] - mn1);
                float p3 = exp2a(sacc[nt][3] - mn1);
                sacc[nt][0] = p0; sacc[nt][1] = p1;
                sacc[nt][2] = p2; sacc[nt][3] = p3;
                ls0 += p0 + p1; ls1 += p2 + p3;
            }
            ls0 += __shfl_xor_sync(0xffffffffu, ls0, 1);
            ls0 += __shfl_xor_sync(0xffffffffu, ls0, 2);
            ls1 += __shfl_xor_sync(0xffffffffu, ls1, 1);
            ls1 += __shfl_xor_sync(0xffffffffu, ls1, 2);
            l0 = l0 * a0 + ls0;
            l1 = l1 * a1 + ls1;

#pragma unroll
            for (int nt = 0; nt < 8; nt++) {
                oacc[nt][0] *= a0; oacc[nt][1] *= a0;
                oacc[nt][2] *= a1; oacc[nt][3] *= a1;
            }

#pragma unroll
            for (int kk = 0; kk < 4; kk++) {
                uint32_t pa0 = h2pack(sacc[2 * kk][0],     sacc[2 * kk][1]);
                uint32_t pa1 = h2pack(sacc[2 * kk][2],     sacc[2 * kk][3]);
                uint32_t pa2 = h2pack(sacc[2 * kk + 1][0], sacc[2 * kk + 1][1]);
                uint32_t pa3 = h2pack(sacc[2 * kk + 1][2], sacc[2 * kk + 1][3]);
#pragma unroll
                for (int nt = 0; nt < 8; nt++) {
                    uint32_t b0 = Vb[(nt * 8 + g) * FSTR + kk * 8 + tg];
                    uint32_t b1 = Vb[(nt * 8 + g) * FSTR + kk * 8 + tg + 4];
                    mma_f16(oacc[nt][0], oacc[nt][1], oacc[nt][2], oacc[nt][3],
                            pa0, pa1, pa2, pa3, b0, b1);
                }
            }
        }

        if (kb + 1 < nbt) CP_WAIT0();
        __syncthreads();
    }

    float inv0 = 1.f / l0, inv1 = 1.f / l1;
    int b_ = bh >> 4, h_ = bh & 15;
    int r0 = wrow + g, r1 = wrow + g + 8;
    __half* o0 = Out + ((size_t)b_ * SEQ + r0) * EMBED + h_ * 64;
    __half* o1 = Out + ((size_t)b_ * SEQ + r1) * EMBED + h_ * 64;
#pragma unroll
    for (int nt = 0; nt < 8; nt++) {
        *reinterpret_cast<uint32_t*>(&o0[nt * 8 + 2 * tg]) =
            h2pack(oacc[nt][0] * inv0, oacc[nt][1] * inv0);
        *reinterpret_cast<uint32_t*>(&o1[nt * 8 + 2 * tg]) =
            h2pack(oacc[nt][2] * inv1, oacc[nt][3] * inv1);
    }
}

// ---------------- launch ----------------
extern "C" void kernel_launch(void* const* d_in, const int* in_sizes, int n_in,
                              void* d_out, int out_size)
{
    const float* query  = (const float*)d_in[0];
    const float* key_in = (const float*)d_in[1];
    const float* value  = (const float*)d_in[2];
    // d_in[3] = mask (int32 tril) — causal applied analytically
    const float* Wq = (const float*)d_in[4];
    const float* bq = (const float*)d_in[5];
    const float* Wk = (const float*)d_in[6];
    const float* bk = (const float*)d_in[7];
    const float* Wv = (const float*)d_in[8];
    const float* bv = (const float*)d_in[9];
    const float* Wo = (const float*)d_in[10];
    const float* bo = (const float*)d_in[11];
    float* out = (float*)d_out;

    __half *gq, *gk, *gv, *ga, *xq, *xk, *xv, *wq, *wk, *wv, *wo;
    cudaGetSymbolAddress((void**)&gq, g_Qh);
    cudaGetSymbolAddress((void**)&gk, g_Kh);
    cudaGetSymbolAddress((void**)&gv, g_Vh);
    cudaGetSymbolAddress((void**)&ga, g_ATTh);
    cudaGetSymbolAddress((void**)&xq, g_Xqh);
    cudaGetSymbolAddress((void**)&xk, g_Xkh);
    cudaGetSymbolAddress((void**)&xv, g_Xvh);
    cudaGetSymbolAddress((void**)&wq, g_Wqh);
    cudaGetSymbolAddress((void**)&wk, g_Wkh);
    cudaGetSymbolAddress((void**)&wv, g_Wvh);
    cudaGetSymbolAddress((void**)&wo, g_Woh);

    cudaFuncSetAttribute(gemm_qkv,
                         cudaFuncAttributeMaxDynamicSharedMemorySize, GT_SMEM_BYTES);
    cudaFuncSetAttribute(gemm_out,
                         cudaFuncAttributeMaxDynamicSharedMemorySize, GT_SMEM_BYTES);

    to_half_all<<<dim3(512, 7), 256>>>(
        (const float4*)query, (const float4*)key_in, (const float4*)value,
        (const float4*)Wq, (const float4*)Wk, (const float4*)Wv, (const float4*)Wo,
        (uint2*)xq, (uint2*)xk, (uint2*)xv,
        (uint2*)wq, (uint2*)wk, (uint2*)wv, (uint2*)wo);

    dim3 gqkv(EMBED / GBN, MTOT / GBM, 3);   // (8, 64, 3)
    gemm_qkv<<<gqkv, 256, GT_SMEM_BYTES>>>(xq, xk, xv, wq, wk, wv,
                                           bq, bk, bv, gq, gk, gv);

    flash_f16<<<dim3(SEQ / 128, BATCH * HEADS), 256>>>(gq, gk, gv, ga);

    gemm_out<<<dim3(EMBED / GBN, MTOT / GBM), 256, GT_SMEM_BYTES>>>(ga, wo, bo, out);
}

// round 16
// speedup vs baseline: 1.2423x; 1.1741x over previous
#include <cuda_runtime.h>
#include <cuda_fp16.h>
#include <cstdint>

#define EMBED    1024
#define HEADS    16
#define HEAD_DIM 64
#define BATCH    4
#define SEQ      2048
#define MTOT     (BATCH * SEQ)

// ---------------- scratch (no allocations allowed) ----------------
__device__ __half g_Qh [(size_t)MTOT * EMBED];
__device__ __half g_Kh [(size_t)MTOT * EMBED];
__device__ __half g_Vh [(size_t)MTOT * EMBED];
__device__ __half g_ATTh[(size_t)MTOT * EMBED];
__device__ __half g_Xqh[(size_t)MTOT * EMBED];
__device__ __half g_Xkh[(size_t)MTOT * EMBED];
__device__ __half g_Xvh[(size_t)MTOT * EMBED];
__device__ __half g_Wqh[(size_t)EMBED * EMBED];
__device__ __half g_Wkh[(size_t)EMBED * EMBED];
__device__ __half g_Wvh[(size_t)EMBED * EMBED];
__device__ __half g_Woh[(size_t)EMBED * EMBED];

// ---------------- helpers ----------------
__device__ __forceinline__ uint32_t h2pack(float a, float b) {
    uint32_t r;
    asm("cvt.rn.f16x2.f32 %0, %1, %2;" : "=r"(r) : "f"(b), "f"(a));
    return r;
}

__device__ __forceinline__ float exp2a(float x) {
    float r;
    asm("ex2.approx.f32 %0, %1;" : "=f"(r) : "f"(x));
    return r;
}

__device__ __forceinline__ void mma_f16(
    float& c0, float& c1, float& c2, float& c3,
    uint32_t a0, uint32_t a1, uint32_t a2, uint32_t a3,
    uint32_t b0, uint32_t b1)
{
    asm volatile(
        "mma.sync.aligned.m16n8k16.row.col.f32.f16.f16.f32 "
        "{%0,%1,%2,%3}, {%4,%5,%6,%7}, {%8,%9}, {%0,%1,%2,%3};\n"
        : "+f"(c0), "+f"(c1), "+f"(c2), "+f"(c3)
        : "r"(a0), "r"(a1), "r"(a2), "r"(a3), "r"(b0), "r"(b1));
}

__device__ __forceinline__ void ldsm4(
    uint32_t& r0, uint32_t& r1, uint32_t& r2, uint32_t& r3, uint32_t addr)
{
    asm volatile("ldmatrix.sync.aligned.m8n8.x4.shared.b16 {%0,%1,%2,%3}, [%4];"
        : "=r"(r0), "=r"(r1), "=r"(r2), "=r"(r3) : "r"(addr));
}

__device__ __forceinline__ uint32_t smem_u32(const void* p) {
    uint32_t a;
    asm("{ .reg .u64 t; cvta.to.shared.u64 t, %1; cvt.u32.u64 %0, t; }"
        : "=r"(a) : "l"(p));
    return a;
}

__device__ __forceinline__ void cp16(uint32_t dst, const void* src) {
    asm volatile("cp.async.cg.shared.global [%0], [%1], 16;" :: "r"(dst), "l"(src));
}
#define CP_COMMIT() asm volatile("cp.async.commit_group;" ::: "memory")
#define CP_WAIT0()  asm volatile("cp.async.wait_group 0;" ::: "memory")
#define CP_WAIT1()  asm volatile("cp.async.wait_group 1;" ::: "memory")

// ---------------- fused fp32 -> fp16 conversion ----------------
__global__ void to_half_all(
    const float4* __restrict__ q,  const float4* __restrict__ k,
    const float4* __restrict__ v,
    const float4* __restrict__ wq, const float4* __restrict__ wk,
    const float4* __restrict__ wv, const float4* __restrict__ wo,
    uint2* __restrict__ oq, uint2* __restrict__ ok, uint2* __restrict__ ov,
    uint2* __restrict__ owq, uint2* __restrict__ owk,
    uint2* __restrict__ owv, uint2* __restrict__ owo)
{
    const float4* in;
    uint2* out;
    int n4;
    switch (blockIdx.y) {
        case 0: in = q;  out = oq;  n4 = MTOT * EMBED / 4; break;
        case 1: in = k;  out = ok;  n4 = MTOT * EMBED / 4; break;
        case 2: in = v;  out = ov;  n4 = MTOT * EMBED / 4; break;
        case 3: in = wq; out = owq; n4 = EMBED * EMBED / 4; break;
        case 4: in = wk; out = owk; n4 = EMBED * EMBED / 4; break;
        case 5: in = wv; out = owv; n4 = EMBED * EMBED / 4; break;
        default: in = wo; out = owo; n4 = EMBED * EMBED / 4; break;
    }
    int i = blockIdx.x * blockDim.x + threadIdx.x;
    int stride = gridDim.x * blockDim.x;
    for (; i < n4; i += stride) {
        float4 x = in[i];
        out[i] = make_uint2(h2pack(x.x, x.y), h2pack(x.z, x.w));
    }
}

// ============================================================
// fp16 GEMM: C = A[.,1024] @ W[.,1024]^T + bias (x scale)
// CTA 128x128, 8 warps (4M x 2N), warp 32x64. BK=64, 3-stage
// cp.async ring (one barrier per 64-K). ldmatrix.x4 fragments.
// smem row = 64 halves + pad: 36 u32 = 144B (LDSM conflict-free).
// ============================================================
#define GBM 128
#define GBN 128
#define GBK 64
#define GSTR 36                         // u32 per row (144B)
#define STG ((GBM + GBN) * GSTR)        // 9216 u32 per stage
#define NSTAGE 3
#define GT_SMEM_BYTES (NSTAGE * STG * 4)   // 110592
#define KITERS (EMBED / GBK)            // 16
#define ROWB 144                        // row bytes
#define MT16 (16 * ROWB)                // 2304

template <int MODE>
__device__ __forceinline__ void gemm_body(
    const __half* __restrict__ A, const __half* __restrict__ W,
    const float* __restrict__ bias, float* __restrict__ Cf,
    __half* __restrict__ Ch, float scale, int bm, int bn, uint32_t* sm)
{
    const int tid  = threadIdx.x;
    const int lane = tid & 31;
    const int warp = tid >> 5;
    const int wm   = warp >> 1;          // 0..3
    const int wn   = warp & 1;           // 0..1
    const int g    = lane >> 2;
    const int tg   = lane & 3;
    const int la7  = lane & 7;
    const int la8  = (lane >> 3) & 1;
    const int la16 = (lane >> 4) & 1;

    const uint32_t sbase = smem_u32(sm);

    // LDSM per-thread offsets
    const uint32_t a_off = (uint32_t)((wm * 32 + (lane & 15)) * ROWB + la16 * 16);
    const uint32_t b_off = (uint32_t)((wn * 64 + la16 * 8 + la7) * ROWB + la8 * 16);

    auto fill = [&](int t) {
        const int s = t % NSTAGE;
        const uint32_t ab = sbase + (uint32_t)(s * STG) * 4;
        const uint32_t bb = ab + (uint32_t)(GBM * GSTR) * 4;
        const __half* Ap = A + (size_t)bm * EMBED + t * GBK;
        const __half* Wp = W + (size_t)bn * EMBED + t * GBK;
#pragma unroll
        for (int i = 0; i < 4; i++) {
            int idx = tid + i * 256;
            int r = idx >> 3, c = idx & 7;
            cp16(ab + (uint32_t)(r * GSTR + c * 4) * 4,
                 Ap + (size_t)r * EMBED + c * 8);
            cp16(bb + (uint32_t)(r * GSTR + c * 4) * 4,
                 Wp + (size_t)r * EMBED + c * 8);
        }
    };

    float acc[2][8][4];
#pragma unroll
    for (int i = 0; i < 2; i++)
#pragma unroll
        for (int j = 0; j < 8; j++)
#pragma unroll
            for (int v = 0; v < 4; v++) acc[i][j][v] = 0.f;

    fill(0); CP_COMMIT();
    fill(1); CP_COMMIT();

    for (int t = 0; t < KITERS; t++) {
        if (t + 1 < KITERS) CP_WAIT1(); else CP_WAIT0();
        __syncthreads();
        if (t + 2 < KITERS) { fill(t + 2); CP_COMMIT(); }

        const uint32_t As_b = sbase + (uint32_t)((t % NSTAGE) * STG) * 4;
        const uint32_t Bs_b = As_b + (uint32_t)(GBM * GSTR) * 4;

#pragma unroll
        for (int ks = 0; ks < 4; ks++) {
            uint32_t af[2][4];
            ldsm4(af[0][0], af[0][1], af[0][2], af[0][3],
                  As_b + a_off + ks * 32);
            ldsm4(af[1][0], af[1][1], af[1][2], af[1][3],
                  As_b + a_off + MT16 + ks * 32);
#pragma unroll
            for (int ntp = 0; ntp < 4; ntp++) {
                uint32_t b0, b1, b2, b3;
                ldsm4(b0, b1, b2, b3, Bs_b + b_off + ntp * MT16 + ks * 32);
#pragma unroll
                for (int mt = 0; mt < 2; mt++) {
                    mma_f16(acc[mt][2 * ntp][0], acc[mt][2 * ntp][1],
                            acc[mt][2 * ntp][2], acc[mt][2 * ntp][3],
                            af[mt][0], af[mt][1], af[mt][2], af[mt][3], b0, b1);
                    mma_f16(acc[mt][2 * ntp + 1][0], acc[mt][2 * ntp + 1][1],
                            acc[mt][2 * ntp + 1][2], acc[mt][2 * ntp + 1][3],
                            af[mt][0], af[mt][1], af[mt][2], af[mt][3], b2, b3);
                }
            }
        }
    }

    // epilogue
#pragma unroll
    for (int mt = 0; mt < 2; mt++) {
#pragma unroll
        for (int nt = 0; nt < 8; nt++) {
            int n = bn + wn * 64 + nt * 8 + tg * 2;
            float bia0 = bias[n], bia1 = bias[n + 1];
#pragma unroll
            for (int half = 0; half < 2; half++) {
                int m = bm + wm * 32 + mt * 16 + g + half * 8;
                float v0 = (acc[mt][nt][half * 2 + 0] + bia0) * scale;
                float v1 = (acc[mt][nt][half * 2 + 1] + bia1) * scale;
                if (MODE == 0) {
                    *reinterpret_cast<float2*>(&Cf[(size_t)m * EMBED + n]) =
                        make_float2(v0, v1);
                } else {
                    int b_ = m >> 11;
                    int s_ = m & (SEQ - 1);
                    int h_ = n >> 6;
                    int d_ = n & 63;
                    *reinterpret_cast<uint32_t*>(
                        &Ch[(((size_t)b_ * HEADS + h_) * SEQ + s_) * HEAD_DIM + d_]) =
                        h2pack(v0, v1);
                }
            }
        }
    }
}

__global__ __launch_bounds__(256, 2) void gemm_qkv(
    const __half* __restrict__ xq, const __half* __restrict__ xk,
    const __half* __restrict__ xv,
    const __half* __restrict__ Wq, const __half* __restrict__ Wk,
    const __half* __restrict__ Wv,
    const float* __restrict__ bq, const float* __restrict__ bk,
    const float* __restrict__ bv,
    __half* __restrict__ oq, __half* __restrict__ ok, __half* __restrict__ ov)
{
    extern __shared__ __align__(16) uint32_t sm[];
    const __half *A, *W;
    const float* bias;
    __half* C;
    float scale = 1.0f;
    if (blockIdx.z == 0) {
        A = xq; W = Wq; bias = bq; C = oq;
        scale = 0.18033688011112042f;     // 1/sqrt(64) * log2(e)
    } else if (blockIdx.z == 1) {
        A = xk; W = Wk; bias = bk; C = ok;
    } else {
        A = xv; W = Wv; bias = bv; C = ov;
    }
    gemm_body<1>(A, W, bias, nullptr, C, scale,
                 blockIdx.y * GBM, blockIdx.x * GBN, sm);
}

__global__ __launch_bounds__(256, 2) void gemm_out(
    const __half* __restrict__ A, const __half* __restrict__ W,
    const float* __restrict__ bias, float* __restrict__ C)
{
    extern __shared__ __align__(16) uint32_t sm[];
    gemm_body<0>(A, W, bias, C, nullptr, 1.0f,
                 blockIdx.y * GBM, blockIdx.x * GBN, sm);
}

// ============================================================
// fp16 flash attention, LDSM fragments
// ============================================================
#define FSTR 36
#define FBUF (64 * FSTR)

__global__ __launch_bounds__(256, 2) void flash_f16(
    const __half* __restrict__ Q, const __half* __restrict__ K,
    const __half* __restrict__ V, __half* __restrict__ Out)
{
    __shared__ __align__(16) uint32_t KS[2 * FBUF];
    __shared__ __align__(16) uint32_t VS[2 * FBUF];

    const int tid  = threadIdx.x;
    const int lane = tid & 31;
    const int w    = tid >> 5;
    const int g    = lane >> 2;
    const int tg   = lane & 3;
    const int la7  = lane & 7;
    const int la8  = (lane >> 3) & 1;
    const int la16 = (lane >> 4) & 1;

    const int qb = (int)gridDim.x - 1 - (int)blockIdx.x;
    const int bh = blockIdx.y;
    const int wrow = qb * 128 + w * 16;

    const uint32_t ksbase = smem_u32(KS);
    const uint32_t vsbase = smem_u32(VS);
    const uint32_t frag_off = (uint32_t)((la16 * 8 + la7) * ROWB + la8 * 16);

    const __half* Kg = K + (size_t)bh * SEQ * HEAD_DIM;
    const __half* Vg = V + (size_t)bh * SEQ * HEAD_DIM;

    const __half* qbase = Q + ((size_t)bh * SEQ + wrow) * HEAD_DIM;
    uint32_t qf[4][4];
#pragma unroll
    for (int kk = 0; kk < 4; kk++) {
        int d0 = kk * 16 + 2 * tg;
        qf[kk][0] = *reinterpret_cast<const uint32_t*>(qbase + (size_t)g * 64 + d0);
        qf[kk][1] = *reinterpret_cast<const uint32_t*>(qbase + (size_t)(g + 8) * 64 + d0);
        qf[kk][2] = *reinterpret_cast<const uint32_t*>(qbase + (size_t)g * 64 + d0 + 8);
        qf[kk][3] = *reinterpret_cast<const uint32_t*>(qbase + (size_t)(g + 8) * 64 + d0 + 8);
    }

    float oacc[8][4];
#pragma unroll
    for (int nt = 0; nt < 8; nt++)
#pragma unroll
        for (int c = 0; c < 4; c++) oacc[nt][c] = 0.f;

    float m0 = -1e30f, m1 = -1e30f, l0 = 0.f, l1 = 0.f;

    const int kkey = tid >> 3;
    const int kchk = tid & 7;
    const int vkey2 = tid & 31;
    const int vd8   = tid >> 5;

    const int nbt = 2 * qb + 2;
    uint4 va, vb;

#pragma unroll
    for (int i = 0; i < 2; i++) {
        int key = kkey + i * 32;
        cp16(ksbase + (key * FSTR + kchk * 4) * 4, Kg + (size_t)key * 64 + kchk * 8);
    }
    CP_COMMIT();
    va = *reinterpret_cast<const uint4*>(Vg + (size_t)(2 * vkey2) * 64 + vd8 * 8);
    vb = *reinterpret_cast<const uint4*>(Vg + (size_t)(2 * vkey2 + 1) * 64 + vd8 * 8);
    {
        const uint32_t* au = reinterpret_cast<const uint32_t*>(&va);
        const uint32_t* bu = reinterpret_cast<const uint32_t*>(&vb);
#pragma unroll
        for (int j = 0; j < 8; j++) {
            uint32_t pk = (j & 1) ? __byte_perm(au[j >> 1], bu[j >> 1], 0x7632)
                                  : __byte_perm(au[j >> 1], bu[j >> 1], 0x5410);
            VS[(vd8 * 8 + j) * FSTR + vkey2] = pk;
        }
    }
    if (nbt > 1) {
        va = *reinterpret_cast<const uint4*>(Vg + (size_t)(64 + 2 * vkey2) * 64 + vd8 * 8);
        vb = *reinterpret_cast<const uint4*>(Vg + (size_t)(64 + 2 * vkey2 + 1) * 64 + vd8 * 8);
    }
    CP_WAIT0();
    __syncthreads();

    for (int kb = 0; kb < nbt; kb++) {
        const int s = kb & 1;
        const int ks = kb * 64;

        if (kb + 1 < nbt) {
            const int ksn = ks + 64;
#pragma unroll
            for (int i = 0; i < 2; i++) {
                int key = kkey + i * 32;
                cp16(ksbase + ((s ^ 1) * FBUF + key * FSTR + kchk * 4) * 4,
                     Kg + (size_t)(ksn + key) * 64 + kchk * 8);
            }
            CP_COMMIT();
            const uint32_t* au = reinterpret_cast<const uint32_t*>(&va);
            const uint32_t* bu = reinterpret_cast<const uint32_t*>(&vb);
            uint32_t* Vw = VS + (s ^ 1) * FBUF;
#pragma unroll
            for (int j = 0; j < 8; j++) {
                uint32_t pk = (j & 1) ? __byte_perm(au[j >> 1], bu[j >> 1], 0x7632)
                                      : __byte_perm(au[j >> 1], bu[j >> 1], 0x5410);
                Vw[(vd8 * 8 + j) * FSTR + vkey2] = pk;
            }
            if (kb + 2 < nbt) {
                const int ks2 = ks + 128;
                va = *reinterpret_cast<const uint4*>(
                    Vg + (size_t)(ks2 + 2 * vkey2) * 64 + vd8 * 8);
                vb = *reinterpret_cast<const uint4*>(
                    Vg + (size_t)(ks2 + 2 * vkey2 + 1) * 64 + vd8 * 8);
            }
        }

        const uint32_t Kb_b = ksbase + (uint32_t)(s * FBUF) * 4;
        const uint32_t Vb_b = vsbase + (uint32_t)(s * FBUF) * 4;

        if (ks <= wrow + 15) {
            float sacc[8][4];
#pragma unroll
            for (int nt = 0; nt < 8; nt++)
#pragma unroll
                for (int c = 0; c < 4; c++) sacc[nt][c] = 0.f;

#pragma unroll
            for (int kk = 0; kk < 4; kk++) {
#pragma unroll
                for (int ntp = 0; ntp < 4; ntp++) {
                    uint32_t b0, b1, b2, b3;
                    ldsm4(b0, b1, b2, b3, Kb_b + frag_off + ntp * MT16 + kk * 32);
                    mma_f16(sacc[2 * ntp][0], sacc[2 * ntp][1],
                            sacc[2 * ntp][2], sacc[2 * ntp][3],
                            qf[kk][0], qf[kk][1], qf[kk][2], qf[kk][3], b0, b1);
                    mma_f16(sacc[2 * ntp + 1][0], sacc[2 * ntp + 1][1],
                            sacc[2 * ntp + 1][2], sacc[2 * ntp + 1][3],
                            qf[kk][0], qf[kk][1], qf[kk][2], qf[kk][3], b2, b3);
                }
            }

            if (ks + 64 > wrow) {
#pragma unroll
                for (int nt = 0; nt < 8; nt++) {
                    int col = ks + nt * 8 + 2 * tg;
                    if (col     > wrow + g)     sacc[nt][0] = -1e30f;
                    if (col + 1 > wrow + g)     sacc[nt][1] = -1e30f;
                    if (col     > wrow + g + 8) sacc[nt][2] = -1e30f;
                    if (col + 1 > wrow + g + 8) sacc[nt][3] = -1e30f;
                }
            }

            float rm0 = -1e30f, rm1 = -1e30f;
#pragma unroll
            for (int nt = 0; nt < 8; nt++) {
                rm0 = fmaxf(rm0, fmaxf(sacc[nt][0], sacc[nt][1]));
                rm1 = fmaxf(rm1, fmaxf(sacc[nt][2], sacc[nt][3]));
            }
            rm0 = fmaxf(rm0, __shfl_xor_sync(0xffffffffu, rm0, 1));
            rm0 = fmaxf(rm0, __shfl_xor_sync(0xffffffffu, rm0, 2));
            rm1 = fmaxf(rm1, __shfl_xor_sync(0xffffffffu, rm1, 1));
            rm1 = fmaxf(rm1, __shfl_xor_sync(0xffffffffu, rm1, 2));

            float mn0 = fmaxf(m0, rm0), mn1 = fmaxf(m1, rm1);
            float a0 = exp2a(m0 - mn0), a1 = exp2a(m1 - mn1);
            m0 = mn0; m1 = mn1;

            float ls0 = 0.f, ls1 = 0.f;
#pragma unroll
            for (int nt = 0; nt < 8; nt++) {
                float p0 = exp2a(sacc[nt][0] - mn0);
                float p1 = exp2a(sacc[nt][1] - mn0);
                float p2 = exp2a(sacc[nt][2] - mn1);
                float p3 = exp2a(sacc[nt][3] - mn1);
                sacc[nt][0] = p0; sacc[nt][1] = p1;
                sacc[nt][2] = p2; sacc[nt][3] = p3;
                ls0 += p0 + p1; ls1 += p2 + p3;
            }
            ls0 += __shfl_xor_sync(0xffffffffu, ls0, 1);
            ls0 += __shfl_xor_sync(0xffffffffu, ls0, 2);
            ls1 += __shfl_xor_sync(0xffffffffu, ls1, 1);
            ls1 += __shfl_xor_sync(0xffffffffu, ls1, 2);
            l0 = l0 * a0 + ls0;
            l1 = l1 * a1 + ls1;

#pragma unroll
            for (int nt = 0; nt < 8; nt++) {
                oacc[nt][0] *= a0; oacc[nt][1] *= a0;
                oacc[nt][2] *= a1; oacc[nt][3] *= a1;
            }

#pragma unroll
            for (int kk = 0; kk < 4; kk++) {
                uint32_t pa0 = h2pack(sacc[2 * kk][0],     sacc[2 * kk][1]);
                uint32_t pa1 = h2pack(sacc[2 * kk][2],     sacc[2 * kk][3]);
                uint32_t pa2 = h2pack(sacc[2 * kk + 1][0], sacc[2 * kk + 1][1]);
                uint32_t pa3 = h2pack(sacc[2 * kk + 1][2], sacc[2 * kk + 1][3]);
#pragma unroll
                for (int ntp = 0; ntp < 4; ntp++) {
                    uint32_t b0, b1, b2, b3;
                    ldsm4(b0, b1, b2, b3, Vb_b + frag_off + ntp * MT16 + kk * 32);
                    mma_f16(oacc[2 * ntp][0], oacc[2 * ntp][1],
                            oacc[2 * ntp][2], oacc[2 * ntp][3],
                            pa0, pa1, pa2, pa3, b0, b1);
                    mma_f16(oacc[2 * ntp + 1][0], oacc[2 * ntp + 1][1],
                            oacc[2 * ntp + 1][2], oacc[2 * ntp + 1][3],
                            pa0, pa1, pa2, pa3, b2, b3);
                }
            }
        }

        if (kb + 1 < nbt) CP_WAIT0();
        __syncthreads();
    }

    float inv0 = 1.f / l0, inv1 = 1.f / l1;
    int b_ = bh >> 4, h_ = bh & 15;
    int r0 = wrow + g, r1 = wrow + g + 8;
    __half* o0 = Out + ((size_t)b_ * SEQ + r0) * EMBED + h_ * 64;
    __half* o1 = Out + ((size_t)b_ * SEQ + r1) * EMBED + h_ * 64;
#pragma unroll
    for (int nt = 0; nt < 8; nt++) {
        *reinterpret_cast<uint32_t*>(&o0[nt * 8 + 2 * tg]) =
            h2pack(oacc[nt][0] * inv0, oacc[nt][1] * inv0);
        *reinterpret_cast<uint32_t*>(&o1[nt * 8 + 2 * tg]) =
            h2pack(oacc[nt][2] * inv1, oacc[nt][3] * inv1);
    }
}

// ---------------- launch ----------------
extern "C" void kernel_launch(void* const* d_in, const int* in_sizes, int n_in,
                              void* d_out, int out_size)
{
    const float* query  = (const float*)d_in[0];
    const float* key_in = (const float*)d_in[1];
    const float* value  = (const float*)d_in[2];
    // d_in[3] = mask (int32 tril) — causal applied analytically
    const float* Wq = (const float*)d_in[4];
    const float* bq = (const float*)d_in[5];
    const float* Wk = (const float*)d_in[6];
    const float* bk = (const float*)d_in[7];
    const float* Wv = (const float*)d_in[8];
    const float* bv = (const float*)d_in[9];
    const float* Wo = (const float*)d_in[10];
    const float* bo = (const float*)d_in[11];
    float* out = (float*)d_out;

    __half *gq, *gk, *gv, *ga, *xq, *xk, *xv, *wq, *wk, *wv, *wo;
    cudaGetSymbolAddress((void**)&gq, g_Qh);
    cudaGetSymbolAddress((void**)&gk, g_Kh);
    cudaGetSymbolAddress((void**)&gv, g_Vh);
    cudaGetSymbolAddress((void**)&ga, g_ATTh);
    cudaGetSymbolAddress((void**)&xq, g_Xqh);
    cudaGetSymbolAddress((void**)&xk, g_Xkh);
    cudaGetSymbolAddress((void**)&xv, g_Xvh);
    cudaGetSymbolAddress((void**)&wq, g_Wqh);
    cudaGetSymbolAddress((void**)&wk, g_Wkh);
    cudaGetSymbolAddress((void**)&wv, g_Wvh);
    cudaGetSymbolAddress((void**)&wo, g_Woh);

    cudaFuncSetAttribute(gemm_qkv,
                         cudaFuncAttributeMaxDynamicSharedMemorySize, GT_SMEM_BYTES);
    cudaFuncSetAttribute(gemm_out,
                         cudaFuncAttributeMaxDynamicSharedMemorySize, GT_SMEM_BYTES);

    to_half_all<<<dim3(512, 7), 256>>>(
        (const float4*)query, (const float4*)key_in, (const float4*)value,
        (const float4*)Wq, (const float4*)Wk, (const float4*)Wv, (const float4*)Wo,
        (uint2*)xq, (uint2*)xk, (uint2*)xv,
        (uint2*)wq, (uint2*)wk, (uint2*)wv, (uint2*)wo);

    dim3 gqkv(EMBED / GBN, MTOT / GBM, 3);   // (8, 64, 3)
    gemm_qkv<<<gqkv, 256, GT_SMEM_BYTES>>>(xq, xk, xv, wq, wk, wv,
                                           bq, bk, bv, gq, gk, gv);

    flash_f16<<<dim3(SEQ / 128, BATCH * HEADS), 256>>>(gq, gk, gv, ga);

    gemm_out<<<dim3(EMBED / GBN, MTOT / GBM), 256, GT_SMEM_BYTES>>>(ga, wo, bo, out);
}